// round 14
// baseline (speedup 1.0000x reference)
#include <cuda_runtime.h>
#include <math.h>

#define NB 592
#define NT (NB * 256)

// ---------------- scratch (device globals; no allocation) ----------------
__device__ float g_h0[1024], g_h1[1024], g_h2[1024];
__device__ float g_acc_qkv[5120];
__device__ float g_scores[8 * 2048];
__device__ __align__(16) float g_acc_attn[4096];
__device__ float g_acc_o[1024];
__device__ float g_acc_gu[8192];
__device__ float g_acc_mlp[1024];
__device__ float g_acc_pg[256];
__device__ float g_acc_pli[1024];
__device__ __align__(16) float g_vcur[512];
__device__ __align__(16) float g_k13[256], g_v13[256], g_k14[512], g_v14[512];
__device__ unsigned g_cnt = 0, g_gen = 0;

// ---------------- grid barrier (counter + generation, raw spin) ----------------
__device__ __forceinline__ void gridbar() {
    __syncthreads();
    if (threadIdx.x == 0) {
        volatile unsigned* vg = &g_gen;
        unsigned gen = *vg;               // read BEFORE arriving
        __threadfence();
        if (atomicAdd(&g_cnt, 1u) == NB - 1) {
            g_cnt = 0;
            __threadfence();
            *vg = gen + 1;
        } else {
            while (*vg == gen) { }
        }
        __threadfence();
    }
    __syncthreads();
}

// ---------------- helpers ----------------
__device__ __forceinline__ float bsum(float v, float* sred) {
    int tid = threadIdx.x;
    #pragma unroll
    for (int o = 16; o; o >>= 1) v += __shfl_xor_sync(0xffffffff, v, o);
    if ((tid & 31) == 0) sred[tid >> 5] = v;
    __syncthreads();
    if (tid == 0) {
        float t = sred[0];
        #pragma unroll
        for (int i = 1; i < 8; i++) t += sred[i];
        sred[0] = t;
    }
    __syncthreads();
    float r = sred[0];
    __syncthreads();
    return r;
}

__device__ __forceinline__ float gelu_tanh(float x) {
    float x3 = x * x * x;
    return 0.5f * x * (1.f + tanhf(0.7978845608028654f * (x + 0.044715f * x3)));
}

__device__ __forceinline__ void fma4(float4& a, float x, const float4 w) {
    a.x += x * w.x; a.y += x * w.y; a.z += x * w.z; a.w += x * w.w;
}

__device__ __forceinline__ void atomic4(float* dst, float4 a) {
    atomicAdd(dst + 0, a.x);
    atomicAdd(dst + 1, a.y);
    atomicAdd(dst + 2, a.z);
    atomicAdd(dst + 3, a.w);
}

// ---------------- the megakernel ----------------
__global__ __launch_bounds__(256, 4) void mega(
    const float* __restrict__ embed,
    const float* __restrict__ cos_s, const float* __restrict__ sin_s,
    const float* __restrict__ cos_f, const float* __restrict__ sin_f,
    const float* __restrict__ ln_in, const float* __restrict__ ln_pa,
    const float* __restrict__ ln_pff, const float* __restrict__ ln_postff,
    const float* __restrict__ ln_ppli,
    const float* __restrict__ qn_w, const float* __restrict__ kn_w,
    const float* __restrict__ Wq, const float* __restrict__ Wk,
    const float* __restrict__ Wv, const float* __restrict__ Wo,
    const float* __restrict__ Wg, const float* __restrict__ Wu,
    const float* __restrict__ Wd, const float* __restrict__ Wpg,
    const float* __restrict__ Wpp,
    const float* __restrict__ lscal, const float* __restrict__ kv,
    const float* __restrict__ plc, const float* __restrict__ img,
    const int* __restrict__ ids, const int* __restrict__ pid,
    float* __restrict__ out, int do_copy)
{
    __shared__ __align__(16) float xs[4096];   // qf in scores stage; x-vector otherwise
    __shared__ __align__(16) float kc[512];
    __shared__ __align__(16) float vc[512];
    __shared__ float sred[8];
    __shared__ float sstat[16];                // mx[8], inv[8]

    int tid = threadIdx.x, bid = blockIdx.x;
    int gtid = bid * 256 + tid;
    int wid = tid >> 5, lane = tid & 31;
    int pos = pid[0];

    // ================= S0: embed + zero acc_qkv =================
    {
        int id = ids[0];
        float iv[4]; float sa = 0.f;
        #pragma unroll
        for (int i = 0; i < 4; i++) { iv[i] = img[tid + i * 256]; sa += fabsf(iv[i]); }
        sa = bsum(sa, sred);
        if (bid == 0) {
            const float* er = embed + (size_t)id * 1024;
            bool isimg = sa > 0.f;
            #pragma unroll
            for (int i = 0; i < 4; i++) {
                int idx = tid + i * 256;
                g_h0[idx] = isimg ? iv[i] : er[idx] * 32.0f;
            }
        }
        for (int z = gtid; z < 5120; z += NT) g_acc_qkv[z] = 0.f;
    }
    gridbar();

    for (int l = 0; l < 15; l++) {
        int full = ((l + 1) % 5 == 0);
        int hd = full ? 512 : 256;
        int lhd = full ? 9 : 8;
        const float* ct = full ? cos_f : cos_s;
        const float* st = full ? sin_f : sin_s;

        // ================= S1: h-finish + rms + QKV gemv =================
        {
            float h0v[4];
            if (l == 0) {
                #pragma unroll
                for (int i = 0; i < 4; i++) h0v[i] = g_h0[tid + i * 256];
            } else {
                const float* lw = ln_ppli + (size_t)(l - 1) * 1024;
                float pv[4]; float ss = 0.f;
                #pragma unroll
                for (int i = 0; i < 4; i++) { pv[i] = g_acc_pli[tid + i * 256]; ss += pv[i] * pv[i]; }
                ss = bsum(ss, sred);
                float r = rsqrtf(ss / 1024.f + 1e-6f);
                float sc = lscal[l - 1];
                #pragma unroll
                for (int i = 0; i < 4; i++) {
                    int idx = tid + i * 256;
                    h0v[i] = (g_h2[idx] + pv[i] * r * (1.f + lw[idx])) * sc;
                }
                if (bid == 0)
                    #pragma unroll
                    for (int i = 0; i < 4; i++) g_h0[tid + i * 256] = h0v[i];
            }
            {
                float ss = 0.f;
                #pragma unroll
                for (int i = 0; i < 4; i++) ss += h0v[i] * h0v[i];
                ss = bsum(ss, sred);
                float r = rsqrtf(ss / 1024.f + 1e-6f);
                const float* lw = ln_in + (size_t)l * 1024;
                #pragma unroll
                for (int i = 0; i < 4; i++) { int idx = tid + i * 256; xs[idx] = h0v[i] * r * (1.f + lw[idx]); }
            }
            __syncthreads();

            int O4 = (10 * hd) >> 2;          // 640 / 1280
            int total = O4 << 7;              // KC=128, chunk=8
            int qs = 8 * hd;
            for (int t = gtid; t < total; t += NT) {
                int c = t / O4; int o4 = t - c * O4;
                int o = o4 << 2;
                const float* wb; int stride;
                if (o < qs) {
                    int hh = o >> lhd, d = o & (hd - 1);
                    wb = Wq + (size_t)l * 4194304 + hh * 512 + d; stride = 4096;
                } else if (o < qs + hd) {
                    wb = Wk + (size_t)l * 524288 + (o - qs); stride = 512;
                } else {
                    wb = Wv + (size_t)l * 524288 + (o - qs - hd); stride = 512;
                }
                int e0 = c << 3;
                const float* wp = wb + (size_t)e0 * stride;
                float4 acc = {0.f, 0.f, 0.f, 0.f};
                #pragma unroll
                for (int e = 0; e < 8; e++) { float4 w = *(const float4*)wp; fma4(acc, xs[e0 + e], w); wp += stride; }
                atomic4(&g_acc_qkv[o], acc);
            }
        }
        gridbar();

        // ================= S2: q/k/v finalize + rope + scores =================
        {
            for (int z = gtid; z < 1024; z += NT) g_acc_pli[z] = 0.f;
            for (int z = gtid; z < 4096; z += NT) g_acc_attn[z] = 0.f;

            float* qf = xs;
            int half = hd >> 1;
            const float* cr = ct + (size_t)pos * hd;
            const float* sr = st + (size_t)pos * hd;
            // q rms per head
            {
                const float* qraw = g_acc_qkv + (size_t)wid * hd;
                float ss = 0.f;
                for (int i = lane; i < hd; i += 32) { float v = qraw[i]; ss += v * v; }
                #pragma unroll
                for (int o = 16; o; o >>= 1) ss += __shfl_xor_sync(0xffffffff, ss, o);
                float r = rsqrtf(ss / (float)hd + 1e-6f);
                const float* qw = qn_w + (size_t)l * 512;
                for (int i = lane; i < hd; i += 32) qf[wid * hd + i] = qraw[i] * r * (1.f + qw[i]);
            }
            // k rms
            {
                float ss = 0.f;
                for (int i = tid; i < hd; i += 256) { float v = g_acc_qkv[8 * hd + i]; ss += v * v; }
                ss = bsum(ss, sred);
                float r = rsqrtf(ss / (float)hd + 1e-6f);
                const float* kw = kn_w + (size_t)l * 512;
                for (int i = tid; i < hd; i += 256) kc[i] = g_acc_qkv[8 * hd + i] * r * (1.f + kw[i]);
            }
            // v norm
            {
                float ss = 0.f;
                for (int i = tid; i < hd; i += 256) { float v = g_acc_qkv[9 * hd + i]; ss += v * v; }
                ss = bsum(ss, sred);
                float r = rsqrtf(ss / (float)hd + 1e-6f);
                for (int i = tid; i < hd; i += 256) vc[i] = g_acc_qkv[9 * hd + i] * r;
            }
            __syncthreads();
            // rope (static-index regs to avoid local memory)
            float tq[16], tk[2];
            int nq = (8 * hd) >> 8, nk = hd >> 8;
            #pragma unroll
            for (int i = 0; i < 16; i++) if (i < nq) {
                int idx = tid + i * 256;
                int h = idx >> lhd, d = idx & (hd - 1);
                float x = qf[idx];
                float rot = (d < half) ? -qf[h * hd + d + half] : qf[h * hd + d - half];
                tq[i] = x * cr[d] + rot * sr[d];
            }
            #pragma unroll
            for (int i = 0; i < 2; i++) if (i < nk) {
                int d = tid + i * 256;
                float x = kc[d];
                float rot = (d < half) ? -kc[d + half] : kc[d - half];
                tk[i] = x * cr[d] + rot * sr[d];
            }
            __syncthreads();
            #pragma unroll
            for (int i = 0; i < 16; i++) if (i < nq) qf[tid + i * 256] = tq[i];
            #pragma unroll
            for (int i = 0; i < 2; i++) if (i < nk) kc[tid + i * 256] = tk[i];
            __syncthreads();
            if (bid == 0) {
                #pragma unroll
                for (int i = 0; i < 2; i++) if (i < nk) g_vcur[tid + i * 256] = vc[tid + i * 256];
                if (l == 13) { g_k13[tid] = kc[tid]; g_v13[tid] = vc[tid]; }
                if (l == 14) {
                    #pragma unroll
                    for (int i = 0; i < 2; i++) {
                        g_k14[tid + i * 256] = kc[tid + i * 256];
                        g_v14[tid + i * 256] = vc[tid + i * 256];
                    }
                }
            }
            // scores
            int it = hd >> 7;
            for (int j = bid * 8 + wid; j <= pos; j += NB * 8) {
                const float4* Kr = (j == pos) ? (const float4*)kc
                                              : (const float4*)(kv + ((size_t)l * 2048 + j) * 512);
                float a[8] = {0, 0, 0, 0, 0, 0, 0, 0};
                #pragma unroll
                for (int t = 0; t < 4; t++) if (t < it) {
                    int i4 = lane + t * 32;
                    float4 kvv = Kr[i4];
                    #pragma unroll
                    for (int h = 0; h < 8; h++) {
                        float4 q = *(const float4*)&qf[h * hd + i4 * 4];
                        a[h] += q.x * kvv.x + q.y * kvv.y + q.z * kvv.z + q.w * kvv.w;
                    }
                }
                #pragma unroll
                for (int h = 0; h < 8; h++) {
                    float t = a[h];
                    #pragma unroll
                    for (int o = 16; o; o >>= 1) t += __shfl_xor_sync(0xffffffff, t, o);
                    if (lane == 0) g_scores[h * 2048 + j] = t;
                }
            }
        }
        gridbar();

        // ================= S4: softmax stats (redundant) + weighted V (2 passes x 4 heads) =================
        {
            {
                const float* sc = g_scores + (size_t)wid * 2048;
                float mx = -1e30f;
                for (int j = lane; j <= pos; j += 32) mx = fmaxf(mx, sc[j]);
                #pragma unroll
                for (int o = 16; o; o >>= 1) mx = fmaxf(mx, __shfl_xor_sync(0xffffffff, mx, o));
                float se = 0.f;
                for (int j = lane; j <= pos; j += 32) se += __expf(sc[j] - mx);
                #pragma unroll
                for (int o = 16; o; o >>= 1) se += __shfl_xor_sync(0xffffffff, se, o);
                if (lane == 0) { sstat[wid] = mx; sstat[8 + wid] = 1.f / se; }
            }
            __syncthreads();
            int ld4 = lhd - 2;
            int D4m = (hd >> 2) - 1;
            int NC = (pos + 8) >> 3;          // ceil((pos+1)/8)
            int per = NC << ld4;
            int total = per << 1;
            const float4* Vb = (const float4*)(kv + (size_t)(15 + l) * 2048 * 512);
            for (int t = gtid; t < total; t += NT) {
                int pass = (t >= per);
                int tt = pass ? (t - per) : t;
                int hb = pass << 2;
                int c = tt >> ld4; int d4 = tt & D4m;
                float mx0 = sstat[hb + 0], mx1 = sstat[hb + 1], mx2 = sstat[hb + 2], mx3 = sstat[hb + 3];
                float iv0 = sstat[8 + hb + 0], iv1 = sstat[8 + hb + 1], iv2 = sstat[8 + hb + 2], iv3 = sstat[8 + hb + 3];
                float4 a0 = {0,0,0,0}, a1 = {0,0,0,0}, a2 = {0,0,0,0}, a3 = {0,0,0,0};
                int j0 = c * 8;
                int jm = (pos < j0 + 7) ? pos : (j0 + 7);
                for (int j = j0; j <= jm; j++) {
                    const float4* vr = (j == pos) ? (const float4*)g_vcur : (Vb + (size_t)j * 128);
                    float4 v = vr[d4];
                    fma4(a0, __expf(g_scores[(hb + 0) * 2048 + j] - mx0) * iv0, v);
                    fma4(a1, __expf(g_scores[(hb + 1) * 2048 + j] - mx1) * iv1, v);
                    fma4(a2, __expf(g_scores[(hb + 2) * 2048 + j] - mx2) * iv2, v);
                    fma4(a3, __expf(g_scores[(hb + 3) * 2048 + j] - mx3) * iv3, v);
                }
                atomic4(&g_acc_attn[(hb + 0) * hd + d4 * 4], a0);
                atomic4(&g_acc_attn[(hb + 1) * hd + d4 * 4], a1);
                atomic4(&g_acc_attn[(hb + 2) * hd + d4 * 4], a2);
                atomic4(&g_acc_attn[(hb + 3) * hd + d4 * 4], a3);
            }
            for (int z = gtid; z < 1024; z += NT) g_acc_o[z] = 0.f;
        }
        gridbar();

        // ================= S5: Wo gemv =================
        {
            int N = 8 * hd;
            for (int i = tid; i < N; i += 256) xs[i] = g_acc_attn[i];
            __syncthreads();
            int KC = N >> 3;                  // chunk = 8
            int total = KC << 8;
            for (int t = gtid; t < total; t += NT) {
                int o4 = t & 255; int c = t >> 8;
                int i0 = c << 3;
                int row0 = (i0 >> lhd) * 512 + (i0 & (hd - 1));
                const float* wp = Wo + (size_t)l * 4194304 + (size_t)row0 * 1024 + (o4 << 2);
                float4 acc = {0.f, 0.f, 0.f, 0.f};
                #pragma unroll
                for (int i = 0; i < 8; i++) { float4 w = *(const float4*)wp; fma4(acc, xs[i0 + i], w); wp += 1024; }
                atomic4(&g_acc_o[o4 << 2], acc);
            }
            for (int z = gtid; z < 8192; z += NT) g_acc_gu[z] = 0.f;
        }
        gridbar();

        // ================= S6: residual + rms + FF gate/up gemv =================
        {
            float ov[4], h1v[4];
            float ss = 0.f;
            #pragma unroll
            for (int i = 0; i < 4; i++) { ov[i] = g_acc_o[tid + i * 256]; ss += ov[i] * ov[i]; }
            ss = bsum(ss, sred);
            float r = rsqrtf(ss / 1024.f + 1e-6f);
            const float* wpa = ln_pa + (size_t)l * 1024;
            #pragma unroll
            for (int i = 0; i < 4; i++) { int idx = tid + i * 256; h1v[i] = g_h0[idx] + ov[i] * r * (1.f + wpa[idx]); }
            if (bid == 0)
                #pragma unroll
                for (int i = 0; i < 4; i++) g_h1[tid + i * 256] = h1v[i];
            float s2 = 0.f;
            #pragma unroll
            for (int i = 0; i < 4; i++) s2 += h1v[i] * h1v[i];
            s2 = bsum(s2, sred);
            float r2 = rsqrtf(s2 / 1024.f + 1e-6f);
            const float* wpf = ln_pff + (size_t)l * 1024;
            #pragma unroll
            for (int i = 0; i < 4; i++) { int idx = tid + i * 256; xs[idx] = h1v[i] * r2 * (1.f + wpf[idx]); }
            __syncthreads();

            int total = 2048 << 6;            // O4=2048, KC=64, chunk 16
            for (int t = gtid; t < total; t += NT) {
                int o4 = t & 2047; int c = t >> 11;
                int o = o4 << 2;
                const float* wb = (o < 4096) ? (Wg + (size_t)l * 4194304 + o)
                                             : (Wu + (size_t)l * 4194304 + (o - 4096));
                int e0 = c << 4;
                const float* wp = wb + (size_t)e0 * 4096;
                float4 acc = {0.f, 0.f, 0.f, 0.f};
                #pragma unroll
                for (int e = 0; e < 16; e++) { float4 w = *(const float4*)wp; fma4(acc, xs[e0 + e], w); wp += 4096; }
                atomic4(&g_acc_gu[o], acc);
            }
            for (int z = gtid; z < 1024; z += NT) g_acc_mlp[z] = 0.f;
        }
        gridbar();

        // ================= S7: gelu*up + FF down gemv =================
        {
            for (int i = tid; i < 4096; i += 256)
                xs[i] = gelu_tanh(g_acc_gu[i]) * g_acc_gu[4096 + i];
            __syncthreads();
            int total = 256 << 8;             // O4=256, KC=256, chunk 16
            for (int t = gtid; t < total; t += NT) {
                int o4 = t & 255; int c = t >> 8;
                int i0 = c << 4;
                const float* wp = Wd + (size_t)l * 4194304 + (size_t)i0 * 1024 + (o4 << 2);
                float4 acc = {0.f, 0.f, 0.f, 0.f};
                #pragma unroll
                for (int i = 0; i < 16; i++) { float4 w = *(const float4*)wp; fma4(acc, xs[i0 + i], w); wp += 1024; }
                atomic4(&g_acc_mlp[o4 << 2], acc);
            }
            for (int z = gtid; z < 256; z += NT) g_acc_pg[z] = 0.f;
        }
        gridbar();

        // ================= S8: residual + rms + PLI gate gemv =================
        {
            float mv[4];
            float ss = 0.f;
            #pragma unroll
            for (int i = 0; i < 4; i++) { mv[i] = g_acc_mlp[tid + i * 256]; ss += mv[i] * mv[i]; }
            ss = bsum(ss, sred);
            float r = rsqrtf(ss / 1024.f + 1e-6f);
            const float* w = ln_postff + (size_t)l * 1024;
            #pragma unroll
            for (int i = 0; i < 4; i++) {
                int idx = tid + i * 256;
                float h2 = g_h1[idx] + mv[i] * r * (1.f + w[idx]);
                xs[idx] = h2;
                if (bid == 0) g_h2[idx] = h2;
            }
            __syncthreads();
            int total = 64 << 8;              // O4=64, KC=256, chunk 4
            for (int t = gtid; t < total; t += NT) {
                int o4 = t & 63; int c = t >> 6;
                int e0 = c << 2;
                const float* wp = Wpg + (size_t)l * 262144 + (size_t)e0 * 256 + (o4 << 2);
                float4 acc = {0.f, 0.f, 0.f, 0.f};
                #pragma unroll
                for (int e = 0; e < 4; e++) { float4 wv = *(const float4*)wp; fma4(acc, xs[e0 + e], wv); wp += 256; }
                atomic4(&g_acc_pg[o4 << 2], acc);
            }
            for (int z = gtid; z < 5120; z += NT) g_acc_qkv[z] = 0.f;
        }
        gridbar();

        // ================= S9: PLI proj gemv =================
        {
            xs[tid] = gelu_tanh(g_acc_pg[tid]) * plc[(size_t)l * 256 + tid];
            __syncthreads();
            int total = 256 << 6;             // O4=256, KC=64, chunk 4
            for (int t = gtid; t < total; t += NT) {
                int o4 = t & 255; int c = t >> 8;
                int e0 = c << 2;
                const float* wp = Wpp + (size_t)l * 262144 + (size_t)e0 * 1024 + (o4 << 2);
                float4 acc = {0.f, 0.f, 0.f, 0.f};
                #pragma unroll
                for (int e = 0; e < 4; e++) { float4 w = *(const float4*)wp; fma4(acc, xs[e0 + e], w); wp += 1024; }
                atomic4(&g_acc_pli[o4 << 2], acc);
            }
        }
        gridbar();
    }

    // ================= final: h out + kv copies =================
    if (bid == 0) {
        const float* w = ln_ppli + (size_t)14 * 1024;
        float pv[4]; float ss = 0.f;
        #pragma unroll
        for (int i = 0; i < 4; i++) { pv[i] = g_acc_pli[tid + i * 256]; ss += pv[i] * pv[i]; }
        ss = bsum(ss, sred);
        float r = rsqrtf(ss / 1024.f + 1e-6f);
        float sc = lscal[14];
        #pragma unroll
        for (int i = 0; i < 4; i++) {
            int idx = tid + i * 256;
            out[idx] = (g_h2[idx] + pv[i] * r * (1.f + w[idx])) * sc;
        }
    }
    if (do_copy) {
        const float4* kv4 = (const float4*)kv;
        float4* out4 = (float4*)(out + 1024);
        for (int i = gtid; i < 786432; i += NT) {
            float4 v;
            if (i < 131072) {
                int j = i >> 6, d4 = i & 63;
                v = (j == pos) ? ((const float4*)g_k13)[d4]
                               : kv4[((size_t)13 * 2048 + j) * 128 + d4];
            } else if (i < 262144) {
                int t = i - 131072; int j = t >> 6, d4 = t & 63;
                v = (j == pos) ? ((const float4*)g_v13)[d4]
                               : kv4[((size_t)28 * 2048 + j) * 128 + d4];
            } else if (i < 524288) {
                int t = i - 262144; int j = t >> 7, d4 = t & 127;
                v = (j == pos) ? ((const float4*)g_k14)[d4]
                               : kv4[((size_t)14 * 2048 + j) * 128 + d4];
            } else {
                int t = i - 524288; int j = t >> 7, d4 = t & 127;
                v = (j == pos) ? ((const float4*)g_v14)[d4]
                               : kv4[((size_t)29 * 2048 + j) * 128 + d4];
            }
            out4[i] = v;
        }
    }
}

// ---------------- host ----------------
extern "C" void kernel_launch(void* const* d_in, const int* in_sizes, int n_in,
                              void* d_out, int out_size) {
    const float* embed     = (const float*)d_in[0];
    const float* cos_s     = (const float*)d_in[1];
    const float* sin_s     = (const float*)d_in[2];
    const float* cos_f     = (const float*)d_in[3];
    const float* sin_f     = (const float*)d_in[4];
    const float* ln_in     = (const float*)d_in[5];
    const float* ln_pa     = (const float*)d_in[6];
    const float* ln_pff    = (const float*)d_in[7];
    const float* ln_postff = (const float*)d_in[8];
    const float* ln_ppli   = (const float*)d_in[9];
    const float* qn_w      = (const float*)d_in[10];
    const float* kn_w      = (const float*)d_in[11];
    const float* Wq        = (const float*)d_in[12];
    const float* Wk        = (const float*)d_in[13];
    const float* Wv        = (const float*)d_in[14];
    const float* Wo        = (const float*)d_in[15];
    const float* Wg        = (const float*)d_in[16];
    const float* Wu        = (const float*)d_in[17];
    const float* Wd        = (const float*)d_in[18];
    const float* Wpg       = (const float*)d_in[19];
    const float* Wpp       = (const float*)d_in[20];
    const float* lscal     = (const float*)d_in[21];
    const float* kv        = (const float*)d_in[22];
    const float* plc       = (const float*)d_in[23];
    const float* img       = (const float*)d_in[24];
    const int*   ids       = (const int*)d_in[27];
    const int*   pid       = (const int*)d_in[28];
    float* out = (float*)d_out;

    int do_copy = (out_size >= 3146752) ? 1 : 0;
    mega<<<NB, 256>>>(embed, cos_s, sin_s, cos_f, sin_f,
                      ln_in, ln_pa, ln_pff, ln_postff, ln_ppli,
                      qn_w, kn_w, Wq, Wk, Wv, Wo, Wg, Wu, Wd, Wpg, Wpp,
                      lscal, kv, plc, img, ids, pid, out, do_copy);
}

// round 15
// speedup vs baseline: 1.0443x; 1.0443x over previous
#include <cuda_runtime.h>
#include <math.h>

#define NB 592
#define NT (NB * 256)

// ---------------- scratch (device globals; no allocation) ----------------
__device__ float g_h0[1024], g_h1[1024], g_h2[1024];
__device__ float g_acc_qkv[5120];
__device__ float g_scores[8 * 2048];
__device__ __align__(16) float g_acc_attn[4096];
__device__ float g_acc_o[1024];
__device__ float g_acc_gu[8192];
__device__ float g_acc_mlp[1024];
__device__ float g_acc_pg[256];
__device__ float g_acc_pli[1024];
__device__ __align__(16) float g_vcur[512];
__device__ __align__(16) float g_k13[256], g_v13[256], g_k14[512], g_v14[512];
__device__ unsigned g_cnt = 0, g_gen = 0;

// ---------------- grid barrier (counter + generation, raw spin) ----------------
__device__ __forceinline__ void gridbar() {
    __syncthreads();
    if (threadIdx.x == 0) {
        volatile unsigned* vg = &g_gen;
        unsigned gen = *vg;               // read BEFORE arriving
        __threadfence();
        if (atomicAdd(&g_cnt, 1u) == NB - 1) {
            g_cnt = 0;
            __threadfence();
            *vg = gen + 1;
        } else {
            while (*vg == gen) { }
        }
        __threadfence();
    }
    __syncthreads();
}

// ---------------- helpers ----------------
__device__ __forceinline__ float bsum(float v, float* sred) {
    int tid = threadIdx.x;
    #pragma unroll
    for (int o = 16; o; o >>= 1) v += __shfl_xor_sync(0xffffffff, v, o);
    if ((tid & 31) == 0) sred[tid >> 5] = v;
    __syncthreads();
    if (tid == 0) {
        float t = sred[0];
        #pragma unroll
        for (int i = 1; i < 8; i++) t += sred[i];
        sred[0] = t;
    }
    __syncthreads();
    float r = sred[0];
    __syncthreads();
    return r;
}

__device__ __forceinline__ float gelu_tanh(float x) {
    float x3 = x * x * x;
    return 0.5f * x * (1.f + tanhf(0.7978845608028654f * (x + 0.044715f * x3)));
}

__device__ __forceinline__ void fma4(float4& a, float x, const float4 w) {
    a.x += x * w.x; a.y += x * w.y; a.z += x * w.z; a.w += x * w.w;
}

__device__ __forceinline__ void atomic4(float* dst, float4 a) {
    atomicAdd(dst + 0, a.x);
    atomicAdd(dst + 1, a.y);
    atomicAdd(dst + 2, a.z);
    atomicAdd(dst + 3, a.w);
}

// ---------------- the megakernel ----------------
__global__ __launch_bounds__(256, 4) void mega(
    const float* __restrict__ embed,
    const float* __restrict__ cos_s, const float* __restrict__ sin_s,
    const float* __restrict__ cos_f, const float* __restrict__ sin_f,
    const float* __restrict__ ln_in, const float* __restrict__ ln_pa,
    const float* __restrict__ ln_pff, const float* __restrict__ ln_postff,
    const float* __restrict__ ln_ppli,
    const float* __restrict__ qn_w, const float* __restrict__ kn_w,
    const float* __restrict__ Wq, const float* __restrict__ Wk,
    const float* __restrict__ Wv, const float* __restrict__ Wo,
    const float* __restrict__ Wg, const float* __restrict__ Wu,
    const float* __restrict__ Wd, const float* __restrict__ Wpg,
    const float* __restrict__ Wpp,
    const float* __restrict__ lscal, const float* __restrict__ kv,
    const float* __restrict__ plc, const float* __restrict__ img,
    const int* __restrict__ ids, const int* __restrict__ pid,
    float* __restrict__ out, int do_copy)
{
    __shared__ __align__(16) float xs[4096];   // qf in scores stage; x-vector otherwise
    __shared__ __align__(16) float kc[512];
    __shared__ __align__(16) float vc[512];
    __shared__ float sred[8];
    __shared__ float sstat[16];                // mx[8], inv[8]

    int tid = threadIdx.x, bid = blockIdx.x;
    int gtid = bid * 256 + tid;
    int wid = tid >> 5, lane = tid & 31;
    int pos = pid[0];

    // ================= S0: embed + zero acc_qkv =================
    {
        int id = ids[0];
        float iv[4]; float sa = 0.f;
        #pragma unroll
        for (int i = 0; i < 4; i++) { iv[i] = img[tid + i * 256]; sa += fabsf(iv[i]); }
        sa = bsum(sa, sred);
        if (bid == 0) {
            const float* er = embed + (size_t)id * 1024;
            bool isimg = sa > 0.f;
            #pragma unroll
            for (int i = 0; i < 4; i++) {
                int idx = tid + i * 256;
                g_h0[idx] = isimg ? iv[i] : er[idx] * 32.0f;
            }
        }
        for (int z = gtid; z < 5120; z += NT) g_acc_qkv[z] = 0.f;
    }
    gridbar();

    for (int l = 0; l < 15; l++) {
        int full = ((l + 1) % 5 == 0);
        int hd = full ? 512 : 256;
        int lhd = full ? 9 : 8;
        const float* ct = full ? cos_f : cos_s;
        const float* st = full ? sin_f : sin_s;

        // ================= S1: h-finish + rms + QKV gemv =================
        {
            float h0v[4];
            if (l == 0) {
                #pragma unroll
                for (int i = 0; i < 4; i++) h0v[i] = g_h0[tid + i * 256];
            } else {
                const float* lw = ln_ppli + (size_t)(l - 1) * 1024;
                float pv[4]; float ss = 0.f;
                #pragma unroll
                for (int i = 0; i < 4; i++) { pv[i] = g_acc_pli[tid + i * 256]; ss += pv[i] * pv[i]; }
                ss = bsum(ss, sred);
                float r = rsqrtf(ss / 1024.f + 1e-6f);
                float sc = lscal[l - 1];
                #pragma unroll
                for (int i = 0; i < 4; i++) {
                    int idx = tid + i * 256;
                    h0v[i] = (g_h2[idx] + pv[i] * r * (1.f + lw[idx])) * sc;
                }
                if (bid == 0)
                    #pragma unroll
                    for (int i = 0; i < 4; i++) g_h0[tid + i * 256] = h0v[i];
            }
            {
                float ss = 0.f;
                #pragma unroll
                for (int i = 0; i < 4; i++) ss += h0v[i] * h0v[i];
                ss = bsum(ss, sred);
                float r = rsqrtf(ss / 1024.f + 1e-6f);
                const float* lw = ln_in + (size_t)l * 1024;
                #pragma unroll
                for (int i = 0; i < 4; i++) { int idx = tid + i * 256; xs[idx] = h0v[i] * r * (1.f + lw[idx]); }
            }
            __syncthreads();

            int O4 = (10 * hd) >> 2;          // 640 / 1280
            int total = O4 << 7;              // KC=128, chunk=8
            int qs = 8 * hd;
            for (int t = gtid; t < total; t += NT) {
                int c = t / O4; int o4 = t - c * O4;
                int o = o4 << 2;
                const float* wb; int stride;
                if (o < qs) {
                    int hh = o >> lhd, d = o & (hd - 1);
                    wb = Wq + (size_t)l * 4194304 + hh * 512 + d; stride = 4096;
                } else if (o < qs + hd) {
                    wb = Wk + (size_t)l * 524288 + (o - qs); stride = 512;
                } else {
                    wb = Wv + (size_t)l * 524288 + (o - qs - hd); stride = 512;
                }
                int e0 = c << 3;
                const float* wp = wb + (size_t)e0 * stride;
                float4 acc = {0.f, 0.f, 0.f, 0.f};
                #pragma unroll
                for (int e = 0; e < 8; e++) { float4 w = *(const float4*)wp; fma4(acc, xs[e0 + e], w); wp += stride; }
                atomic4(&g_acc_qkv[o], acc);
            }
        }
        gridbar();

        // ================= S2: q/k/v finalize + rope + scores =================
        {
            for (int z = gtid; z < 1024; z += NT) g_acc_pli[z] = 0.f;
            for (int z = gtid; z < 4096; z += NT) g_acc_attn[z] = 0.f;

            float* qf = xs;
            int half = hd >> 1;
            const float* cr = ct + (size_t)pos * hd;
            const float* sr = st + (size_t)pos * hd;
            // q rms per head
            {
                const float* qraw = g_acc_qkv + (size_t)wid * hd;
                float ss = 0.f;
                for (int i = lane; i < hd; i += 32) { float v = qraw[i]; ss += v * v; }
                #pragma unroll
                for (int o = 16; o; o >>= 1) ss += __shfl_xor_sync(0xffffffff, ss, o);
                float r = rsqrtf(ss / (float)hd + 1e-6f);
                const float* qw = qn_w + (size_t)l * 512;
                for (int i = lane; i < hd; i += 32) qf[wid * hd + i] = qraw[i] * r * (1.f + qw[i]);
            }
            // k rms
            {
                float ss = 0.f;
                for (int i = tid; i < hd; i += 256) { float v = g_acc_qkv[8 * hd + i]; ss += v * v; }
                ss = bsum(ss, sred);
                float r = rsqrtf(ss / (float)hd + 1e-6f);
                const float* kw = kn_w + (size_t)l * 512;
                for (int i = tid; i < hd; i += 256) kc[i] = g_acc_qkv[8 * hd + i] * r * (1.f + kw[i]);
            }
            // v norm
            {
                float ss = 0.f;
                for (int i = tid; i < hd; i += 256) { float v = g_acc_qkv[9 * hd + i]; ss += v * v; }
                ss = bsum(ss, sred);
                float r = rsqrtf(ss / (float)hd + 1e-6f);
                for (int i = tid; i < hd; i += 256) vc[i] = g_acc_qkv[9 * hd + i] * r;
            }
            __syncthreads();
            // rope (static-index regs to avoid local memory)
            float tq[16], tk[2];
            int nq = (8 * hd) >> 8, nk = hd >> 8;
            #pragma unroll
            for (int i = 0; i < 16; i++) if (i < nq) {
                int idx = tid + i * 256;
                int h = idx >> lhd, d = idx & (hd - 1);
                float x = qf[idx];
                float rot = (d < half) ? -qf[h * hd + d + half] : qf[h * hd + d - half];
                tq[i] = x * cr[d] + rot * sr[d];
            }
            #pragma unroll
            for (int i = 0; i < 2; i++) if (i < nk) {
                int d = tid + i * 256;
                float x = kc[d];
                float rot = (d < half) ? -kc[d + half] : kc[d - half];
                tk[i] = x * cr[d] + rot * sr[d];
            }
            __syncthreads();
            #pragma unroll
            for (int i = 0; i < 16; i++) if (i < nq) qf[tid + i * 256] = tq[i];
            #pragma unroll
            for (int i = 0; i < 2; i++) if (i < nk) kc[tid + i * 256] = tk[i];
            __syncthreads();
            if (bid == 0) {
                #pragma unroll
                for (int i = 0; i < 2; i++) if (i < nk) g_vcur[tid + i * 256] = vc[tid + i * 256];
                if (l == 13) { g_k13[tid] = kc[tid]; g_v13[tid] = vc[tid]; }
                if (l == 14) {
                    #pragma unroll
                    for (int i = 0; i < 2; i++) {
                        g_k14[tid + i * 256] = kc[tid + i * 256];
                        g_v14[tid + i * 256] = vc[tid + i * 256];
                    }
                }
            }
            // scores
            int it = hd >> 7;
            for (int j = bid * 8 + wid; j <= pos; j += NB * 8) {
                const float4* Kr = (j == pos) ? (const float4*)kc
                                              : (const float4*)(kv + ((size_t)l * 2048 + j) * 512);
                float a[8] = {0, 0, 0, 0, 0, 0, 0, 0};
                #pragma unroll
                for (int t = 0; t < 4; t++) if (t < it) {
                    int i4 = lane + t * 32;
                    float4 kvv = Kr[i4];
                    #pragma unroll
                    for (int h = 0; h < 8; h++) {
                        float4 q = *(const float4*)&qf[h * hd + i4 * 4];
                        a[h] += q.x * kvv.x + q.y * kvv.y + q.z * kvv.z + q.w * kvv.w;
                    }
                }
                #pragma unroll
                for (int h = 0; h < 8; h++) {
                    float t = a[h];
                    #pragma unroll
                    for (int o = 16; o; o >>= 1) t += __shfl_xor_sync(0xffffffff, t, o);
                    if (lane == 0) g_scores[h * 2048 + j] = t;
                }
            }
        }
        gridbar();

        // ================= S4: softmax stats (redundant) + weighted V (2 passes x 4 heads) =================
        {
            {
                const float* sc = g_scores + (size_t)wid * 2048;
                float mx = -1e30f;
                for (int j = lane; j <= pos; j += 32) mx = fmaxf(mx, sc[j]);
                #pragma unroll
                for (int o = 16; o; o >>= 1) mx = fmaxf(mx, __shfl_xor_sync(0xffffffff, mx, o));
                float se = 0.f;
                for (int j = lane; j <= pos; j += 32) se += __expf(sc[j] - mx);
                #pragma unroll
                for (int o = 16; o; o >>= 1) se += __shfl_xor_sync(0xffffffff, se, o);
                if (lane == 0) { sstat[wid] = mx; sstat[8 + wid] = 1.f / se; }
            }
            __syncthreads();
            int ld4 = lhd - 2;
            int D4m = (hd >> 2) - 1;
            int NC = (pos + 8) >> 3;          // ceil((pos+1)/8)
            int per = NC << ld4;
            int total = per << 1;
            const float4* Vb = (const float4*)(kv + (size_t)(15 + l) * 2048 * 512);
            for (int t = gtid; t < total; t += NT) {
                int pass = (t >= per);
                int tt = pass ? (t - per) : t;
                int hb = pass << 2;
                int c = tt >> ld4; int d4 = tt & D4m;
                float mx0 = sstat[hb + 0], mx1 = sstat[hb + 1], mx2 = sstat[hb + 2], mx3 = sstat[hb + 3];
                float iv0 = sstat[8 + hb + 0], iv1 = sstat[8 + hb + 1], iv2 = sstat[8 + hb + 2], iv3 = sstat[8 + hb + 3];
                float4 a0 = {0,0,0,0}, a1 = {0,0,0,0}, a2 = {0,0,0,0}, a3 = {0,0,0,0};
                int j0 = c * 8;
                int jm = (pos < j0 + 7) ? pos : (j0 + 7);
                for (int j = j0; j <= jm; j++) {
                    const float4* vr = (j == pos) ? (const float4*)g_vcur : (Vb + (size_t)j * 128);
                    float4 v = vr[d4];
                    fma4(a0, __expf(g_scores[(hb + 0) * 2048 + j] - mx0) * iv0, v);
                    fma4(a1, __expf(g_scores[(hb + 1) * 2048 + j] - mx1) * iv1, v);
                    fma4(a2, __expf(g_scores[(hb + 2) * 2048 + j] - mx2) * iv2, v);
                    fma4(a3, __expf(g_scores[(hb + 3) * 2048 + j] - mx3) * iv3, v);
                }
                atomic4(&g_acc_attn[(hb + 0) * hd + d4 * 4], a0);
                atomic4(&g_acc_attn[(hb + 1) * hd + d4 * 4], a1);
                atomic4(&g_acc_attn[(hb + 2) * hd + d4 * 4], a2);
                atomic4(&g_acc_attn[(hb + 3) * hd + d4 * 4], a3);
            }
            for (int z = gtid; z < 1024; z += NT) g_acc_o[z] = 0.f;
        }
        gridbar();

        // ================= S5: Wo gemv =================
        {
            int N = 8 * hd;
            for (int i = tid; i < N; i += 256) xs[i] = g_acc_attn[i];
            __syncthreads();
            int KC = N >> 3;                  // chunk = 8
            int total = KC << 8;
            for (int t = gtid; t < total; t += NT) {
                int o4 = t & 255; int c = t >> 8;
                int i0 = c << 3;
                int row0 = (i0 >> lhd) * 512 + (i0 & (hd - 1));
                const float* wp = Wo + (size_t)l * 4194304 + (size_t)row0 * 1024 + (o4 << 2);
                float4 acc = {0.f, 0.f, 0.f, 0.f};
                #pragma unroll
                for (int i = 0; i < 8; i++) { float4 w = *(const float4*)wp; fma4(acc, xs[i0 + i], w); wp += 1024; }
                atomic4(&g_acc_o[o4 << 2], acc);
            }
            for (int z = gtid; z < 8192; z += NT) g_acc_gu[z] = 0.f;
        }
        gridbar();

        // ================= S6: residual + rms + FF gate/up gemv =================
        {
            float ov[4], h1v[4];
            float ss = 0.f;
            #pragma unroll
            for (int i = 0; i < 4; i++) { ov[i] = g_acc_o[tid + i * 256]; ss += ov[i] * ov[i]; }
            ss = bsum(ss, sred);
            float r = rsqrtf(ss / 1024.f + 1e-6f);
            const float* wpa = ln_pa + (size_t)l * 1024;
            #pragma unroll
            for (int i = 0; i < 4; i++) { int idx = tid + i * 256; h1v[i] = g_h0[idx] + ov[i] * r * (1.f + wpa[idx]); }
            if (bid == 0)
                #pragma unroll
                for (int i = 0; i < 4; i++) g_h1[tid + i * 256] = h1v[i];
            float s2 = 0.f;
            #pragma unroll
            for (int i = 0; i < 4; i++) s2 += h1v[i] * h1v[i];
            s2 = bsum(s2, sred);
            float r2 = rsqrtf(s2 / 1024.f + 1e-6f);
            const float* wpf = ln_pff + (size_t)l * 1024;
            #pragma unroll
            for (int i = 0; i < 4; i++) { int idx = tid + i * 256; xs[idx] = h1v[i] * r2 * (1.f + wpf[idx]); }
            __syncthreads();

            int total = 2048 << 6;            // O4=2048, KC=64, chunk 16
            for (int t = gtid; t < total; t += NT) {
                int o4 = t & 2047; int c = t >> 11;
                int o = o4 << 2;
                const float* wb = (o < 4096) ? (Wg + (size_t)l * 4194304 + o)
                                             : (Wu + (size_t)l * 4194304 + (o - 4096));
                int e0 = c << 4;
                const float* wp = wb + (size_t)e0 * 4096;
                float4 acc = {0.f, 0.f, 0.f, 0.f};
                #pragma unroll
                for (int e = 0; e < 16; e++) { float4 w = *(const float4*)wp; fma4(acc, xs[e0 + e], w); wp += 4096; }
                atomic4(&g_acc_gu[o], acc);
            }
            for (int z = gtid; z < 1024; z += NT) g_acc_mlp[z] = 0.f;
        }
        gridbar();

        // ================= S7: gelu*up + FF down gemv =================
        {
            for (int i = tid; i < 4096; i += 256)
                xs[i] = gelu_tanh(g_acc_gu[i]) * g_acc_gu[4096 + i];
            __syncthreads();
            int total = 256 << 8;             // O4=256, KC=256, chunk 16
            for (int t = gtid; t < total; t += NT) {
                int o4 = t & 255; int c = t >> 8;
                int i0 = c << 4;
                const float* wp = Wd + (size_t)l * 4194304 + (size_t)i0 * 1024 + (o4 << 2);
                float4 acc = {0.f, 0.f, 0.f, 0.f};
                #pragma unroll
                for (int i = 0; i < 16; i++) { float4 w = *(const float4*)wp; fma4(acc, xs[i0 + i], w); wp += 1024; }
                atomic4(&g_acc_mlp[o4 << 2], acc);
            }
            for (int z = gtid; z < 256; z += NT) g_acc_pg[z] = 0.f;
        }
        gridbar();

        // ================= S8: residual + rms + PLI gate gemv =================
        {
            float mv[4];
            float ss = 0.f;
            #pragma unroll
            for (int i = 0; i < 4; i++) { mv[i] = g_acc_mlp[tid + i * 256]; ss += mv[i] * mv[i]; }
            ss = bsum(ss, sred);
            float r = rsqrtf(ss / 1024.f + 1e-6f);
            const float* w = ln_postff + (size_t)l * 1024;
            #pragma unroll
            for (int i = 0; i < 4; i++) {
                int idx = tid + i * 256;
                float h2 = g_h1[idx] + mv[i] * r * (1.f + w[idx]);
                xs[idx] = h2;
                if (bid == 0) g_h2[idx] = h2;
            }
            __syncthreads();
            int total = 64 << 8;              // O4=64, KC=256, chunk 4
            for (int t = gtid; t < total; t += NT) {
                int o4 = t & 63; int c = t >> 6;
                int e0 = c << 2;
                const float* wp = Wpg + (size_t)l * 262144 + (size_t)e0 * 256 + (o4 << 2);
                float4 acc = {0.f, 0.f, 0.f, 0.f};
                #pragma unroll
                for (int e = 0; e < 4; e++) { float4 wv = *(const float4*)wp; fma4(acc, xs[e0 + e], wv); wp += 256; }
                atomic4(&g_acc_pg[o4 << 2], acc);
            }
            for (int z = gtid; z < 5120; z += NT) g_acc_qkv[z] = 0.f;
        }
        gridbar();

        // ================= S9: PLI proj gemv =================
        {
            xs[tid] = gelu_tanh(g_acc_pg[tid]) * plc[(size_t)l * 256 + tid];
            __syncthreads();
            int total = 256 << 6;             // O4=256, KC=64, chunk 4
            for (int t = gtid; t < total; t += NT) {
                int o4 = t & 255; int c = t >> 8;
                int e0 = c << 2;
                const float* wp = Wpp + (size_t)l * 262144 + (size_t)e0 * 1024 + (o4 << 2);
                float4 acc = {0.f, 0.f, 0.f, 0.f};
                #pragma unroll
                for (int e = 0; e < 4; e++) { float4 w = *(const float4*)wp; fma4(acc, xs[e0 + e], w); wp += 1024; }
                atomic4(&g_acc_pli[o4 << 2], acc);
            }
        }
        gridbar();
    }

    // ================= final: h out + kv copies =================
    if (bid == 0) {
        const float* w = ln_ppli + (size_t)14 * 1024;
        float pv[4]; float ss = 0.f;
        #pragma unroll
        for (int i = 0; i < 4; i++) { pv[i] = g_acc_pli[tid + i * 256]; ss += pv[i] * pv[i]; }
        ss = bsum(ss, sred);
        float r = rsqrtf(ss / 1024.f + 1e-6f);
        float sc = lscal[14];
        #pragma unroll
        for (int i = 0; i < 4; i++) {
            int idx = tid + i * 256;
            out[idx] = (g_h2[idx] + pv[i] * r * (1.f + w[idx])) * sc;
        }
    }
    if (do_copy) {
        const float4* kv4 = (const float4*)kv;
        float4* out4 = (float4*)(out + 1024);
        for (int i = gtid; i < 786432; i += NT) {
            float4 v;
            if (i < 131072) {
                int j = i >> 6, d4 = i & 63;
                v = (j == pos) ? ((const float4*)g_k13)[d4]
                               : kv4[((size_t)13 * 2048 + j) * 128 + d4];
            } else if (i < 262144) {
                int t = i - 131072; int j = t >> 6, d4 = t & 63;
                v = (j == pos) ? ((const float4*)g_v13)[d4]
                               : kv4[((size_t)28 * 2048 + j) * 128 + d4];
            } else if (i < 524288) {
                int t = i - 262144; int j = t >> 7, d4 = t & 127;
                v = (j == pos) ? ((const float4*)g_k14)[d4]
                               : kv4[((size_t)14 * 2048 + j) * 128 + d4];
            } else {
                int t = i - 524288; int j = t >> 7, d4 = t & 127;
                v = (j == pos) ? ((const float4*)g_v14)[d4]
                               : kv4[((size_t)29 * 2048 + j) * 128 + d4];
            }
            out4[i] = v;
        }
    }
}

// ---------------- host ----------------
extern "C" void kernel_launch(void* const* d_in, const int* in_sizes, int n_in,
                              void* d_out, int out_size) {
    const float* embed     = (const float*)d_in[0];
    const float* cos_s     = (const float*)d_in[1];
    const float* sin_s     = (const float*)d_in[2];
    const float* cos_f     = (const float*)d_in[3];
    const float* sin_f     = (const float*)d_in[4];
    const float* ln_in     = (const float*)d_in[5];
    const float* ln_pa     = (const float*)d_in[6];
    const float* ln_pff    = (const float*)d_in[7];
    const float* ln_postff = (const float*)d_in[8];
    const float* ln_ppli   = (const float*)d_in[9];
    const float* qn_w      = (const float*)d_in[10];
    const float* kn_w      = (const float*)d_in[11];
    const float* Wq        = (const float*)d_in[12];
    const float* Wk        = (const float*)d_in[13];
    const float* Wv        = (const float*)d_in[14];
    const float* Wo        = (const float*)d_in[15];
    const float* Wg        = (const float*)d_in[16];
    const float* Wu        = (const float*)d_in[17];
    const float* Wd        = (const float*)d_in[18];
    const float* Wpg       = (const float*)d_in[19];
    const float* Wpp       = (const float*)d_in[20];
    const float* lscal     = (const float*)d_in[21];
    const float* kv        = (const float*)d_in[22];
    const float* plc       = (const float*)d_in[23];
    const float* img       = (const float*)d_in[24];
    const int*   ids       = (const int*)d_in[27];
    const int*   pid       = (const int*)d_in[28];
    float* out = (float*)d_out;

    int do_copy = (out_size >= 3146752) ? 1 : 0;
    mega<<<NB, 256>>>(embed, cos_s, sin_s, cos_f, sin_f,
                      ln_in, ln_pa, ln_pff, ln_postff, ln_ppli,
                      qn_w, kn_w, Wq, Wk, Wv, Wo, Wg, Wu, Wd, Wpg, Wpp,
                      lscal, kv, plc, img, ids, pid, out, do_copy);
}